// round 9
// baseline (speedup 1.0000x reference)
#include <cuda_runtime.h>
#include <cuda_fp16.h>
#include <cstdint>

#define PERIODS 12
#define ROWPAD 16          // xs/agg rows: 16 halves = 32B (1 sector)
#define HIDDEN 32
#define MAXN 100000
#define MAXE 1600000

// Scratch (static __device__ — zero-initialized at module load; every launch
// restores the zero-invariant itself, so no init pass is needed).
__device__ float g_deg[MAXN];                             // invariant: 0 between launches
__device__ float g_dinv[MAXN];
__device__ __align__(32) __half g_aggh[MAXN * ROWPAD];    // invariant: 0 between launches
__device__ __align__(32) __half g_xsh[MAXN * ROWPAD];     // xs = dinv*x in fp16

struct Params {
    float vz[HIDDEN], cz[HIDDEN], vh[HIDDEN], ch[HIDDEN], hw[HIDDEN];
    float probs[PERIODS];
    float head_b;
};
__device__ Params g_p;

__device__ __forceinline__ float tanhx(float x) {
    float y;
    asm("tanh.approx.f32 %0, %1;" : "=f"(y) : "f"(x));
    return y;
}

// ---------------------------------------------------------------------------
// Fused: blocks [0, EB) accumulate deg[dst] += ew (from 0; self-loop folded
// into dinv later). Block EB folds the gate MLPs + softmax(attention).
// ---------------------------------------------------------------------------
__global__ void k_deg_params(int e, int eb,
                         const int* __restrict__ dst, const float* __restrict__ ew,
                         const float* __restrict__ att,
                         const float* __restrict__ czw, const float* __restrict__ czb,
                         const float* __restrict__ Lz,  const float* __restrict__ lzb,
                         const float* __restrict__ chw, const float* __restrict__ chb,
                         const float* __restrict__ Lh,  const float* __restrict__ lhb,
                         const float* __restrict__ head_w, const float* __restrict__ head_b) {
    if (blockIdx.x < (unsigned)eb) {
        int i = blockIdx.x * blockDim.x + threadIdx.x;
        if (i < e) atomicAdd(&g_deg[dst[i]], ew[i]);
        return;
    }
    // params block
    int c = threadIdx.x;
    if (c < HIDDEN) {
        float vz = 0.f, cz = 0.f, vh = 0.f, ch = 0.f;
        #pragma unroll
        for (int j = 0; j < HIDDEN; j++) {
            vz += czw[j] * Lz[j * HIDDEN + c];
            cz += czb[j] * Lz[j * HIDDEN + c];
            vh += chw[j] * Lh[j * HIDDEN + c];
            ch += chb[j] * Lh[j * HIDDEN + c];
        }
        g_p.vz[c] = vz;
        g_p.cz[c] = cz + lzb[c];
        g_p.vh[c] = vh;
        g_p.ch[c] = ch + lhb[c];
        g_p.hw[c] = head_w[c];
    }
    if (c == 0) {
        float m = att[0];
        for (int t = 1; t < PERIODS; t++) m = fmaxf(m, att[t]);
        float ex[PERIODS];
        float s = 0.f;
        for (int t = 0; t < PERIODS; t++) { ex[t] = __expf(att[t] - m); s += ex[t]; }
        float inv = 1.0f / s;
        for (int t = 0; t < PERIODS; t++) g_p.probs[t] = ex[t] * inv;
        g_p.head_b = head_b[0];
    }
}

// dinv = (1 + deg)^{-1/2} (self loop folded);  xs_h = fp16(dinv*x);
// resets g_deg to 0 for the next launch.
__global__ void k_dinv_xs(const float4* __restrict__ x, int n) {
    int i = blockIdx.x * blockDim.x + threadIdx.x;
    if (i < n) {
        float di = rsqrtf(1.0f + g_deg[i]);
        g_deg[i] = 0.0f;                          // restore zero-invariant
        g_dinv[i] = di;
        __half2* xshv = (__half2*)(g_xsh + i * ROWPAD);
        #pragma unroll
        for (int k = 0; k < 3; k++) {
            float4 v = x[i * 3 + k];              // x rows tight (12 floats)
            xshv[k * 2 + 0] = __floats2half2_rn(di * v.x, di * v.y);
            xshv[k * 2 + 1] = __floats2half2_rn(di * v.z, di * v.w);
        }
    }
}

// Per edge: agg[dst,:] += ew * xs_h[src,:]
// 1x 32B gather + v4.f16x2 + v2.f16x2 reds (128b ptxas cap — v8 rejected).
// Products computed in f32 (ew stays f32), rounded once to fp16.
__global__ void k_edge(const int* __restrict__ src,
                       const int* __restrict__ dst,
                       const float* __restrict__ ew,
                       int e) {
    int i = blockIdx.x * blockDim.x + threadIdx.x;
    if (i < e) {
        int s = src[i];
        int d = dst[i];
        float c = ew[i];
        const uint4* xp = (const uint4*)(g_xsh + s * ROWPAD);
        uint4 q0 = xp[0];                       // halves 0..7
        uint2 q1 = ((const uint2*)xp)[2];       // halves 8..11
        __half* ap = g_aggh + d * ROWPAD;

        float2 f0 = __half22float2(*(__half2*)&q0.x);
        float2 f1 = __half22float2(*(__half2*)&q0.y);
        float2 f2 = __half22float2(*(__half2*)&q0.z);
        float2 f3 = __half22float2(*(__half2*)&q0.w);
        float2 f4 = __half22float2(*(__half2*)&q1.x);
        float2 f5 = __half22float2(*(__half2*)&q1.y);

        __half2 p0 = __floats2half2_rn(c * f0.x, c * f0.y);
        __half2 p1 = __floats2half2_rn(c * f1.x, c * f1.y);
        __half2 p2 = __floats2half2_rn(c * f2.x, c * f2.y);
        __half2 p3 = __floats2half2_rn(c * f3.x, c * f3.y);
        __half2 p4 = __floats2half2_rn(c * f4.x, c * f4.y);
        __half2 p5 = __floats2half2_rn(c * f5.x, c * f5.y);

        asm volatile("red.global.add.noftz.v4.f16x2 [%0], {%1,%2,%3,%4};"
                     :: "l"(ap),
                        "r"(*(unsigned*)&p0), "r"(*(unsigned*)&p1),
                        "r"(*(unsigned*)&p2), "r"(*(unsigned*)&p3) : "memory");
        asm volatile("red.global.add.noftz.v2.f16x2 [%0], {%1,%2};"
                     :: "l"(ap + 8),
                        "r"(*(unsigned*)&p4), "r"(*(unsigned*)&p5) : "memory");
    }
}

// One warp per node, lane = period for the load; lane = channel for the math.
// a[n,t] = dinv*(agg_fp16[n,t] + dinv*x[n,t])   (self term exact f32)
// (1-Z)*Ht = (0.5 - 0.5*tanh(xz/2)) * tanh(xh)   [2 MUFU per period]
// Resets this node's agg row to 0 for the next launch (hidden under MUFU).
__global__ void k_node(const float* __restrict__ x, float* __restrict__ out, int n) {
    int warp = (blockIdx.x * blockDim.x + threadIdx.x) >> 5;
    int lane = threadIdx.x & 31;
    if (warp >= n) return;

    float di = g_dinv[warp];   // broadcast load
    float aval = 0.f;
    if (lane < PERIODS) {
        float edge = __half2float(g_aggh[warp * ROWPAD + lane]);
        aval = di * (edge + di * x[warp * PERIODS + lane]);
    }
    __syncwarp();
    if (lane < 6)  // restore zero-invariant: halves 0..11 (padding never written)
        ((unsigned*)(g_aggh + warp * ROWPAD))[lane] = 0u;

    float vz = g_p.vz[lane] * 0.5f, cz = g_p.cz[lane] * 0.5f;
    float vh = g_p.vh[lane],        ch = g_p.ch[lane];

    float hacc = 0.f;
    #pragma unroll
    for (int t = 0; t < PERIODS; t++) {
        float a  = __shfl_sync(0xffffffffu, aval, t);
        float tz = tanhx(a * vz + cz);        // tanh(xz/2)
        float th = tanhx(a * vh + ch);        // tanh(xh)
        hacc += g_p.probs[t] * (0.5f - 0.5f * tz) * th;
    }
    float v = fmaxf(hacc, 0.f) * g_p.hw[lane];
    #pragma unroll
    for (int off = 16; off; off >>= 1)
        v += __shfl_xor_sync(0xffffffffu, v, off);
    if (lane == 0) out[warp] = v + g_p.head_b;
}

extern "C" void kernel_launch(void* const* d_in, const int* in_sizes, int n_in,
                              void* d_out, int out_size) {
    const float* x    = (const float*)d_in[0];
    const int*   eidx = (const int*)d_in[1];   // int32 (JAX x64 disabled)
    const float* ew   = (const float*)d_in[2];
    const float* att  = (const float*)d_in[3];
    const float* czw  = (const float*)d_in[4];
    const float* czb  = (const float*)d_in[5];
    const float* lzw  = (const float*)d_in[6];
    const float* lzb  = (const float*)d_in[7];
    // d_in[8..11]: r-gate params — provably unused (H = 0 => H*R = 0)
    const float* chw  = (const float*)d_in[12];
    const float* chb  = (const float*)d_in[13];
    const float* lhw  = (const float*)d_in[14];
    const float* lhb  = (const float*)d_in[15];
    const float* hw   = (const float*)d_in[16];
    const float* hb   = (const float*)d_in[17];
    float* out = (float*)d_out;

    int N = in_sizes[0] / PERIODS;
    int E = in_sizes[2];
    const int* src = eidx;
    const int* dst = eidx + E;

    int EB = (E + 255) / 256;
    k_deg_params<<<EB + 1, 256>>>(E, EB, dst, ew, att, czw, czb, lzw, lzb,
                                  chw, chb, lhw, lhb, hw, hb);
    k_dinv_xs<<<(N + 255) / 256, 256>>>((const float4*)x, N);
    k_edge<<<(E + 255) / 256, 256>>>(src, dst, ew, E);
    k_node<<<(N * 32 + 127) / 128, 128>>>(x, out, N);
}

// round 10
// speedup vs baseline: 1.0559x; 1.0559x over previous
#include <cuda_runtime.h>
#include <cuda_fp16.h>
#include <cstdint>

#define PERIODS 12
#define ROWPAD 16          // xs/agg rows: 16 halves = 32B (1 sector)
#define HIDDEN 32
#define MAXN 100000
#define MAXE 1600000

// Scratch (static __device__ — zero-initialized at module load; every launch
// restores the zero-invariant itself, so no init pass is needed).
__device__ float g_deg[MAXN];                             // invariant: 0 between launches
__device__ float g_dinv[MAXN];
__device__ __align__(32) __half g_aggh[MAXN * ROWPAD];    // invariant: 0 between launches
__device__ __align__(32) __half g_xsh[MAXN * ROWPAD];     // xs = dinv*x in fp16

// Params as a flat float array for easy smem staging:
// [0:32) vz | [32:64) cz | [64:96) vh | [96:128) ch | [128:160) hw
// [160:172) probs | [172] head_b   => 173 floats
#define NPARAMS 173
__device__ float g_p[NPARAMS];

__device__ __forceinline__ float tanhx(float x) {
    float y;
    asm("tanh.approx.f32 %0, %1;" : "=f"(y) : "f"(x));
    return y;
}

// ---------------------------------------------------------------------------
// Fused: blocks [0, EB) accumulate deg[dst] += ew (from 0; self-loop folded
// into dinv later). Block EB folds the gate MLPs + softmax(attention).
// ---------------------------------------------------------------------------
__global__ void k_deg_params(int e, int eb,
                         const int* __restrict__ dst, const float* __restrict__ ew,
                         const float* __restrict__ att,
                         const float* __restrict__ czw, const float* __restrict__ czb,
                         const float* __restrict__ Lz,  const float* __restrict__ lzb,
                         const float* __restrict__ chw, const float* __restrict__ chb,
                         const float* __restrict__ Lh,  const float* __restrict__ lhb,
                         const float* __restrict__ head_w, const float* __restrict__ head_b) {
    if (blockIdx.x < (unsigned)eb) {
        int i = blockIdx.x * blockDim.x + threadIdx.x;
        if (i < e) atomicAdd(&g_deg[dst[i]], ew[i]);
        return;
    }
    // params block
    int c = threadIdx.x;
    if (c < HIDDEN) {
        float vz = 0.f, cz = 0.f, vh = 0.f, ch = 0.f;
        #pragma unroll
        for (int j = 0; j < HIDDEN; j++) {
            vz += czw[j] * Lz[j * HIDDEN + c];
            cz += czb[j] * Lz[j * HIDDEN + c];
            vh += chw[j] * Lh[j * HIDDEN + c];
            ch += chb[j] * Lh[j * HIDDEN + c];
        }
        g_p[c]       = vz * 0.5f;            // pre-halved for the sigmoid->tanh identity
        g_p[32 + c]  = (cz + lzb[c]) * 0.5f;
        g_p[64 + c]  = vh;
        g_p[96 + c]  = ch + lhb[c];
        g_p[128 + c] = head_w[c];
    }
    if (c == 0) {
        float m = att[0];
        for (int t = 1; t < PERIODS; t++) m = fmaxf(m, att[t]);
        float ex[PERIODS];
        float s = 0.f;
        for (int t = 0; t < PERIODS; t++) { ex[t] = __expf(att[t] - m); s += ex[t]; }
        float inv = 1.0f / s;
        for (int t = 0; t < PERIODS; t++) g_p[160 + t] = ex[t] * inv;
        g_p[172] = head_b[0];
    }
}

// dinv = (1 + deg)^{-1/2} (self loop folded);  xs_h = fp16(dinv*x);
// resets g_deg to 0 for the next launch.
__global__ void k_dinv_xs(const float4* __restrict__ x, int n) {
    int i = blockIdx.x * blockDim.x + threadIdx.x;
    if (i < n) {
        float di = rsqrtf(1.0f + g_deg[i]);
        g_deg[i] = 0.0f;                          // restore zero-invariant
        g_dinv[i] = di;
        __half2* xshv = (__half2*)(g_xsh + i * ROWPAD);
        #pragma unroll
        for (int k = 0; k < 3; k++) {
            float4 v = x[i * 3 + k];              // x rows tight (12 floats)
            xshv[k * 2 + 0] = __floats2half2_rn(di * v.x, di * v.y);
            xshv[k * 2 + 1] = __floats2half2_rn(di * v.z, di * v.w);
        }
    }
}

// Per edge: agg[dst,:] += ew * xs_h[src,:]
// 1x 32B gather + v4.f16x2 + v2.f16x2 reds (128b ptxas cap).
// Products computed in f32 (ew stays f32), rounded once to fp16.
__global__ void k_edge(const int* __restrict__ src,
                       const int* __restrict__ dst,
                       const float* __restrict__ ew,
                       int e) {
    int i = blockIdx.x * blockDim.x + threadIdx.x;
    if (i < e) {
        int s = src[i];
        int d = dst[i];
        float c = ew[i];
        const uint4* xp = (const uint4*)(g_xsh + s * ROWPAD);
        uint4 q0 = xp[0];                       // halves 0..7
        uint2 q1 = ((const uint2*)xp)[2];       // halves 8..11
        __half* ap = g_aggh + d * ROWPAD;

        float2 f0 = __half22float2(*(__half2*)&q0.x);
        float2 f1 = __half22float2(*(__half2*)&q0.y);
        float2 f2 = __half22float2(*(__half2*)&q0.z);
        float2 f3 = __half22float2(*(__half2*)&q0.w);
        float2 f4 = __half22float2(*(__half2*)&q1.x);
        float2 f5 = __half22float2(*(__half2*)&q1.y);

        __half2 p0 = __floats2half2_rn(c * f0.x, c * f0.y);
        __half2 p1 = __floats2half2_rn(c * f1.x, c * f1.y);
        __half2 p2 = __floats2half2_rn(c * f2.x, c * f2.y);
        __half2 p3 = __floats2half2_rn(c * f3.x, c * f3.y);
        __half2 p4 = __floats2half2_rn(c * f4.x, c * f4.y);
        __half2 p5 = __floats2half2_rn(c * f5.x, c * f5.y);

        asm volatile("red.global.add.noftz.v4.f16x2 [%0], {%1,%2,%3,%4};"
                     :: "l"(ap),
                        "r"(*(unsigned*)&p0), "r"(*(unsigned*)&p1),
                        "r"(*(unsigned*)&p2), "r"(*(unsigned*)&p3) : "memory");
        asm volatile("red.global.add.noftz.v2.f16x2 [%0], {%1,%2};"
                     :: "l"(ap + 8),
                        "r"(*(unsigned*)&p4), "r"(*(unsigned*)&p5) : "memory");
    }
}

// TWO nodes per warp: lanes 0-11 hold node A's periods, lanes 16-27 node B's.
// Every lane computes its channel for both nodes (independent chains -> 2x ILP).
// Params staged in smem once per block (off the L1/LDG path).
// a[n,t] = dinv*(agg_fp16[n,t] + dinv*x[n,t]); term = (0.5-0.5*tanh(xz/2))*tanh(xh).
// Resets agg rows to 0 for the next launch.
__global__ void k_node(const float* __restrict__ x, float* __restrict__ out, int n) {
    __shared__ float sp[NPARAMS];
    if (threadIdx.x < NPARAMS) sp[threadIdx.x] = g_p[threadIdx.x];
    __syncthreads();

    int warp = (blockIdx.x * blockDim.x + threadIdx.x) >> 5;
    int lane = threadIdx.x & 31;
    int nodeA = warp * 2;
    int nodeB = nodeA + 1;
    if (nodeA >= n) return;
    bool hasB = nodeB < n;

    float diA = g_dinv[nodeA];
    float diB = hasB ? g_dinv[nodeB] : 0.f;
    float aval = 0.f;
    if (lane < PERIODS) {
        float edge = __half2float(g_aggh[nodeA * ROWPAD + lane]);
        aval = diA * (edge + diA * x[nodeA * PERIODS + lane]);
    } else if (lane >= 16 && lane < 16 + PERIODS && hasB) {
        int l = lane - 16;
        float edge = __half2float(g_aggh[nodeB * ROWPAD + l]);
        aval = diB * (edge + diB * x[nodeB * PERIODS + l]);
    }
    __syncwarp();
    // restore zero-invariant: halves 0..11 of each row (padding never written)
    if (lane < 6)
        ((unsigned*)(g_aggh + nodeA * ROWPAD))[lane] = 0u;
    else if (lane >= 16 && lane < 22 && hasB)
        ((unsigned*)(g_aggh + nodeB * ROWPAD))[lane - 16] = 0u;

    float vz = sp[lane],      cz = sp[32 + lane];   // pre-halved
    float vh = sp[64 + lane], ch = sp[96 + lane];

    float hA = 0.f, hB = 0.f;
    #pragma unroll
    for (int t = 0; t < PERIODS; t++) {
        float p  = sp[160 + t];
        float aA = __shfl_sync(0xffffffffu, aval, t);
        float aB = __shfl_sync(0xffffffffu, aval, t + 16);
        float tzA = tanhx(aA * vz + cz);
        float thA = tanhx(aA * vh + ch);
        float tzB = tanhx(aB * vz + cz);
        float thB = tanhx(aB * vh + ch);
        hA += p * ((0.5f - 0.5f * tzA) * thA);
        hB += p * ((0.5f - 0.5f * tzB) * thB);
    }
    float vA = fmaxf(hA, 0.f) * sp[128 + lane];
    float vB = fmaxf(hB, 0.f) * sp[128 + lane];
    #pragma unroll
    for (int off = 16; off; off >>= 1) {
        vA += __shfl_xor_sync(0xffffffffu, vA, off);
        vB += __shfl_xor_sync(0xffffffffu, vB, off);
    }
    if (lane == 0) {
        float hb = sp[172];
        out[nodeA] = vA + hb;
        if (hasB) out[nodeB] = vB + hb;
    }
}

extern "C" void kernel_launch(void* const* d_in, const int* in_sizes, int n_in,
                              void* d_out, int out_size) {
    const float* x    = (const float*)d_in[0];
    const int*   eidx = (const int*)d_in[1];   // int32 (JAX x64 disabled)
    const float* ew   = (const float*)d_in[2];
    const float* att  = (const float*)d_in[3];
    const float* czw  = (const float*)d_in[4];
    const float* czb  = (const float*)d_in[5];
    const float* lzw  = (const float*)d_in[6];
    const float* lzb  = (const float*)d_in[7];
    // d_in[8..11]: r-gate params — provably unused (H = 0 => H*R = 0)
    const float* chw  = (const float*)d_in[12];
    const float* chb  = (const float*)d_in[13];
    const float* lhw  = (const float*)d_in[14];
    const float* lhb  = (const float*)d_in[15];
    const float* hw   = (const float*)d_in[16];
    const float* hb   = (const float*)d_in[17];
    float* out = (float*)d_out;

    int N = in_sizes[0] / PERIODS;
    int E = in_sizes[2];
    const int* src = eidx;
    const int* dst = eidx + E;

    int EB = (E + 255) / 256;
    k_deg_params<<<EB + 1, 256>>>(E, EB, dst, ew, att, czw, czb, lzw, lzb,
                                  chw, chb, lhw, lhb, hw, hb);
    k_dinv_xs<<<(N + 255) / 256, 256>>>((const float4*)x, N);
    k_edge<<<(E + 255) / 256, 256>>>(src, dst, ew, E);

    int pairs = (N + 1) / 2;                       // one warp per 2 nodes
    k_node<<<(pairs * 32 + 255) / 256, 256>>>(x, out, N);
}

// round 12
// speedup vs baseline: 1.0570x; 1.0010x over previous
#include <cuda_runtime.h>
#include <cuda_fp16.h>
#include <cstdint>

#define PERIODS 12
#define ROWPAD 16          // xs/agg rows: 16 halves = 32B (1 sector)
#define HIDDEN 32
#define MAXN 100000
#define MAXE 1600000

// Scratch (static __device__ — zero-initialized at module load; every launch
// restores the zero-invariant itself, so no init pass is needed).
__device__ float g_deg[MAXN];                             // invariant: 0 between launches
__device__ float g_dinv[MAXN];
__device__ __align__(32) __half g_aggh[MAXN * ROWPAD];    // invariant: 0 between launches
__device__ __align__(32) __half g_xsh[MAXN * ROWPAD];     // xs = dinv*x in fp16

// Params as a flat float array for easy smem staging:
// [0:32) vz*0.5 | [32:64) cz*0.5 | [64:96) vh | [96:128) ch | [128:160) hw
// [160:172) probs | [172] head_b   => 173 floats
#define NPARAMS 173
__device__ float g_p[NPARAMS];

__device__ __forceinline__ float tanhx(float x) {
    float y;
    asm("tanh.approx.f32 %0, %1;" : "=f"(y) : "f"(x));
    return y;
}

// ---------------------------------------------------------------------------
// Fused: blocks [0, EB) accumulate deg[dst] += ew (from 0; self-loop folded
// into dinv later). Block EB folds the gate MLPs + softmax(attention).
// ---------------------------------------------------------------------------
__global__ void k_deg_params(int e, int eb,
                         const int* __restrict__ dst, const float* __restrict__ ew,
                         const float* __restrict__ att,
                         const float* __restrict__ czw, const float* __restrict__ czb,
                         const float* __restrict__ Lz,  const float* __restrict__ lzb,
                         const float* __restrict__ chw, const float* __restrict__ chb,
                         const float* __restrict__ Lh,  const float* __restrict__ lhb,
                         const float* __restrict__ head_w, const float* __restrict__ head_b) {
    if (blockIdx.x < (unsigned)eb) {
        int i = blockIdx.x * blockDim.x + threadIdx.x;
        if (i < e) atomicAdd(&g_deg[dst[i]], ew[i]);
        return;
    }
    // params block
    int c = threadIdx.x;
    if (c < HIDDEN) {
        float vz = 0.f, cz = 0.f, vh = 0.f, ch = 0.f;
        #pragma unroll
        for (int j = 0; j < HIDDEN; j++) {
            vz += czw[j] * Lz[j * HIDDEN + c];
            cz += czb[j] * Lz[j * HIDDEN + c];
            vh += chw[j] * Lh[j * HIDDEN + c];
            ch += chb[j] * Lh[j * HIDDEN + c];
        }
        g_p[c]       = vz * 0.5f;            // pre-halved for the sigmoid->tanh identity
        g_p[32 + c]  = (cz + lzb[c]) * 0.5f;
        g_p[64 + c]  = vh;
        g_p[96 + c]  = ch + lhb[c];
        g_p[128 + c] = head_w[c];
    }
    if (c == 0) {
        float m = att[0];
        for (int t = 1; t < PERIODS; t++) m = fmaxf(m, att[t]);
        float ex[PERIODS];
        float s = 0.f;
        for (int t = 0; t < PERIODS; t++) { ex[t] = __expf(att[t] - m); s += ex[t]; }
        float inv = 1.0f / s;
        for (int t = 0; t < PERIODS; t++) g_p[160 + t] = ex[t] * inv;
        g_p[172] = head_b[0];
    }
}

// dinv = (1 + deg)^{-1/2} (self loop folded);  xs_h = fp16(dinv*x);
// resets g_deg to 0 for the next launch.
__global__ void k_dinv_xs(const float4* __restrict__ x, int n) {
    int i = blockIdx.x * blockDim.x + threadIdx.x;
    if (i < n) {
        float di = rsqrtf(1.0f + g_deg[i]);
        g_deg[i] = 0.0f;                          // restore zero-invariant
        g_dinv[i] = di;
        __half2* xshv = (__half2*)(g_xsh + i * ROWPAD);
        #pragma unroll
        for (int k = 0; k < 3; k++) {
            float4 v = x[i * 3 + k];              // x rows tight (12 floats)
            xshv[k * 2 + 0] = __floats2half2_rn(di * v.x, di * v.y);
            xshv[k * 2 + 1] = __floats2half2_rn(di * v.z, di * v.w);
        }
    }
}

// Per edge: agg[dst,:] += ew * xs_h[src,:]
// TWO edges per thread: vectorized int2/float2 stream loads, both gathers
// issued back-to-back (MLP=2), then v4.f16x2 + v2.f16x2 reds per edge.
__device__ __forceinline__ void edge_one(int s, int d, float c) {
    const uint4* xp = (const uint4*)(g_xsh + s * ROWPAD);
    uint4 q0 = xp[0];                       // halves 0..7
    uint2 q1 = ((const uint2*)xp)[2];       // halves 8..11
    __half* ap = g_aggh + d * ROWPAD;

    float2 f0 = __half22float2(*(__half2*)&q0.x);
    float2 f1 = __half22float2(*(__half2*)&q0.y);
    float2 f2 = __half22float2(*(__half2*)&q0.z);
    float2 f3 = __half22float2(*(__half2*)&q0.w);
    float2 f4 = __half22float2(*(__half2*)&q1.x);
    float2 f5 = __half22float2(*(__half2*)&q1.y);

    __half2 p0 = __floats2half2_rn(c * f0.x, c * f0.y);
    __half2 p1 = __floats2half2_rn(c * f1.x, c * f1.y);
    __half2 p2 = __floats2half2_rn(c * f2.x, c * f2.y);
    __half2 p3 = __floats2half2_rn(c * f3.x, c * f3.y);
    __half2 p4 = __floats2half2_rn(c * f4.x, c * f4.y);
    __half2 p5 = __floats2half2_rn(c * f5.x, c * f5.y);

    asm volatile("red.global.add.noftz.v4.f16x2 [%0], {%1,%2,%3,%4};"
                 :: "l"(ap),
                    "r"(*(unsigned*)&p0), "r"(*(unsigned*)&p1),
                    "r"(*(unsigned*)&p2), "r"(*(unsigned*)&p3) : "memory");
    asm volatile("red.global.add.noftz.v2.f16x2 [%0], {%1,%2};"
                 :: "l"(ap + 8),
                    "r"(*(unsigned*)&p4), "r"(*(unsigned*)&p5) : "memory");
}

__global__ void k_edge(const int* __restrict__ src,
                       const int* __restrict__ dst,
                       const float* __restrict__ ew,
                       int e) {
    int i = (blockIdx.x * blockDim.x + threadIdx.x) * 2;
    if (i + 1 < e) {
        int2   s2 = *(const int2*)(src + i);
        int2   d2 = *(const int2*)(dst + i);
        float2 w2 = *(const float2*)(ew + i);
        edge_one(s2.x, d2.x, w2.x);
        edge_one(s2.y, d2.y, w2.y);
    } else if (i < e) {
        edge_one(src[i], dst[i], ew[i]);
    }
}

// TWO nodes per warp: lanes 0-11 compute node A's a-values, lanes 16-27 node B's.
// Pairs (aA, aB) staged in smem as native float2 (8B-aligned!) -> the inner loop
// broadcasts via LDS.64 instead of 24 SHFLs on the critical path.
// a[n,t] = dinv*(agg_fp16[n,t] + dinv*x[n,t]); term = p*(0.5-0.5*tanh(xz/2))*tanh(xh).
// Resets agg rows to 0 for the next launch.
__global__ void k_node(const float* __restrict__ x, float* __restrict__ out, int n) {
    __shared__ float sp[NPARAMS];
    __shared__ float2 sa[8][PERIODS];               // 8 warps/block; float2 => 8B aligned
    if (threadIdx.x < NPARAMS) sp[threadIdx.x] = g_p[threadIdx.x];
    __syncthreads();

    int warp = (blockIdx.x * blockDim.x + threadIdx.x) >> 5;
    int wlocal = (threadIdx.x >> 5);
    int lane = threadIdx.x & 31;
    int nodeA = warp * 2;
    int nodeB = nodeA + 1;
    if (nodeA >= n) return;
    bool hasB = nodeB < n;

    float diA = g_dinv[nodeA];
    float diB = hasB ? g_dinv[nodeB] : 0.f;
    float aval = 0.f;
    if (lane < PERIODS) {
        float edge = __half2float(g_aggh[nodeA * ROWPAD + lane]);
        aval = diA * (edge + diA * x[nodeA * PERIODS + lane]);
    } else if (lane >= 16 && lane < 16 + PERIODS) {
        int l = lane - 16;
        float edge = hasB ? __half2float(g_aggh[nodeB * ROWPAD + l]) : 0.f;
        float xv   = hasB ? x[nodeB * PERIODS + l] : 0.f;
        aval = diB * (edge + diB * xv);
    }
    float bpart = __shfl_down_sync(0xffffffffu, aval, 16);  // lane l gets aB(l)
    if (lane < PERIODS) {
        float2 p; p.x = aval; p.y = bpart;
        sa[wlocal][lane] = p;                       // st.shared.v2 (aligned)
    }
    __syncwarp();
    // restore zero-invariant: halves 0..11 of each row (padding never written)
    if (lane < 6)
        ((unsigned*)(g_aggh + nodeA * ROWPAD))[lane] = 0u;
    else if (lane >= 16 && lane < 22 && hasB)
        ((unsigned*)(g_aggh + nodeB * ROWPAD))[lane - 16] = 0u;

    float vz = sp[lane],      cz = sp[32 + lane];   // pre-halved
    float vh = sp[64 + lane], ch = sp[96 + lane];

    float hA = 0.f, hB = 0.f;
    #pragma unroll
    for (int t = 0; t < PERIODS; t++) {
        float p   = sp[160 + t];
        float2 ab = sa[wlocal][t];                  // broadcast LDS.64
        float tzA = tanhx(ab.x * vz + cz);
        float thA = tanhx(ab.x * vh + ch);
        float tzB = tanhx(ab.y * vz + cz);
        float thB = tanhx(ab.y * vh + ch);
        hA += p * ((0.5f - 0.5f * tzA) * thA);
        hB += p * ((0.5f - 0.5f * tzB) * thB);
    }
    float vA = fmaxf(hA, 0.f) * sp[128 + lane];
    float vB = fmaxf(hB, 0.f) * sp[128 + lane];
    #pragma unroll
    for (int off = 16; off; off >>= 1) {
        vA += __shfl_xor_sync(0xffffffffu, vA, off);
        vB += __shfl_xor_sync(0xffffffffu, vB, off);
    }
    if (lane == 0) {
        float hb = sp[172];
        out[nodeA] = vA + hb;
        if (hasB) out[nodeB] = vB + hb;
    }
}

extern "C" void kernel_launch(void* const* d_in, const int* in_sizes, int n_in,
                              void* d_out, int out_size) {
    const float* x    = (const float*)d_in[0];
    const int*   eidx = (const int*)d_in[1];   // int32 (JAX x64 disabled)
    const float* ew   = (const float*)d_in[2];
    const float* att  = (const float*)d_in[3];
    const float* czw  = (const float*)d_in[4];
    const float* czb  = (const float*)d_in[5];
    const float* lzw  = (const float*)d_in[6];
    const float* lzb  = (const float*)d_in[7];
    // d_in[8..11]: r-gate params — provably unused (H = 0 => H*R = 0)
    const float* chw  = (const float*)d_in[12];
    const float* chb  = (const float*)d_in[13];
    const float* lhw  = (const float*)d_in[14];
    const float* lhb  = (const float*)d_in[15];
    const float* hw   = (const float*)d_in[16];
    const float* hb   = (const float*)d_in[17];
    float* out = (float*)d_out;

    int N = in_sizes[0] / PERIODS;
    int E = in_sizes[2];
    const int* src = eidx;
    const int* dst = eidx + E;

    int EB = (E + 255) / 256;
    k_deg_params<<<EB + 1, 256>>>(E, EB, dst, ew, att, czw, czb, lzw, lzb,
                                  chw, chb, lhw, lhb, hw, hb);
    k_dinv_xs<<<(N + 255) / 256, 256>>>((const float4*)x, N);

    int ethreads = (E + 1) / 2;                    // 2 edges per thread
    k_edge<<<(ethreads + 255) / 256, 256>>>(src, dst, ew, E);

    int pairs = (N + 1) / 2;                       // one warp per 2 nodes
    k_node<<<(pairs * 32 + 255) / 256, 256>>>(x, out, N);
}